// round 2
// baseline (speedup 1.0000x reference)
#include <cuda_runtime.h>
#include <stdint.h>

#define NUM_BINS 256
#define NCH_SAMPLE 3
#define NCH_TOTAL 6
#define NPX (2048 * 4096)

// Scratch (static device globals — no allocations in kernel_launch).
__device__ int           g_hist[NCH_SAMPLE][NUM_BINS];
__device__ float         g_lut[NCH_SAMPLE][NUM_BINS];
__device__ unsigned char g_bins[(size_t)NCH_SAMPLE * NPX];   // 25 MB bin cache

__global__ void zero_hist_kernel() {
    int i = blockIdx.x * blockDim.x + threadIdx.x;
    if (i < NCH_SAMPLE * NUM_BINS) ((int*)g_hist)[i] = 0;
}

// K1: copy target channels (3..5) input -> output. Pure streaming, float4.
__global__ void copy_targets_kernel(const float* __restrict__ img,
                                    float* __restrict__ out, int npx) {
    const int c = blockIdx.y + NCH_SAMPLE;
    const float4* p = (const float4*)(img + (size_t)c * npx);
    float4*       q = (float4*)(out + (size_t)c * npx);
    const int n4 = npx >> 2;
    const int stride = gridDim.x * blockDim.x;
    int i = blockIdx.x * blockDim.x + threadIdx.x;
    for (; i + stride < n4; i += 2 * stride) {
        float4 a = p[i];
        float4 b = p[i + stride];
        q[i] = a;
        q[i + stride] = b;
    }
    if (i < n4) q[i] = p[i];
}

// K2: read samples once; build 4-way replicated smem histograms AND write
// uint8 bins to g_bins (which stays hot in L2 for K4).
__global__ void hist_bin_kernel(const float* __restrict__ img, int npx) {
    __shared__ int sh[4][NUM_BINS];
    const int c = blockIdx.y;
    const int t = threadIdx.x;

    for (int i = t; i < 4 * NUM_BINS; i += blockDim.x) ((int*)sh)[i] = 0;
    __syncthreads();

    const float4* p = (const float4*)(img + (size_t)c * npx);
    uchar4*       b = (uchar4*)(g_bins + (size_t)c * npx);
    const int n4 = npx >> 2;
    const int sub = t & 3;
    const int stride = gridDim.x * blockDim.x;

    for (int i = blockIdx.x * blockDim.x + t; i < n4; i += stride) {
        float4 v = p[i];
        int bx = min(NUM_BINS - 1, max(0, (int)v.x));
        int by = min(NUM_BINS - 1, max(0, (int)v.y));
        int bz = min(NUM_BINS - 1, max(0, (int)v.z));
        int bw = min(NUM_BINS - 1, max(0, (int)v.w));
        b[i] = make_uchar4((unsigned char)bx, (unsigned char)by,
                           (unsigned char)bz, (unsigned char)bw);
        atomicAdd(&sh[sub][bx], 1);
        atomicAdd(&sh[sub][by], 1);
        atomicAdd(&sh[sub][bz], 1);
        atomicAdd(&sh[sub][bw], 1);
    }
    __syncthreads();

    for (int i = t; i < NUM_BINS; i += blockDim.x) {
        int s = sh[0][i] + sh[1][i] + sh[2][i] + sh[3][i];
        if (s) atomicAdd(&g_hist[c][i], s);
    }
}

// K3: exact torchvision/JAX LUT. One 256-thread block per channel.
__global__ void lut_kernel() {
    const int c = blockIdx.x;
    const int t = threadIdx.x;
    __shared__ int hist[NUM_BINS];
    __shared__ int cum[NUM_BINS];
    __shared__ int s_lastnz;

    int h = g_hist[c][t];
    hist[t] = h;
    cum[t] = h;
    if (t == 0) s_lastnz = 0;
    __syncthreads();

    #pragma unroll
    for (int off = 1; off < NUM_BINS; off <<= 1) {
        int tmp = (t >= off) ? cum[t - off] : 0;
        __syncthreads();
        cum[t] += tmp;
        __syncthreads();
    }

    if (h > 0) atomicMax(&s_lastnz, t);
    __syncthreads();

    const int total = cum[NUM_BINS - 1];
    const int last  = s_lastnz;
    const int step  = (total - hist[last]) / (NUM_BINS - 1);

    float outv;
    if (step == 0) {
        outv = (float)t;   // where(step==0, chan, lut[chan]) -> identity LUT
    } else {
        int l = (t == 0) ? 0 : (cum[t - 1] + (step >> 1)) / step;
        l = min(NUM_BINS - 1, max(0, l));
        outv = (float)l;
    }
    g_lut[c][t] = outv;
}

// K4: apply sample channels from the uint8 bin cache (L2-resident).
// Read uchar4 (4B), write float4 (16B).
__global__ void apply_samples_kernel(float* __restrict__ out, int npx) {
    const int c = blockIdx.y;
    __shared__ float lut[NUM_BINS];
    for (int i = threadIdx.x; i < NUM_BINS; i += blockDim.x)
        lut[i] = g_lut[c][i];
    __syncthreads();

    const uchar4* b = (const uchar4*)(g_bins + (size_t)c * npx);
    float4*       q = (float4*)(out + (size_t)c * npx);
    const int n4 = npx >> 2;
    const int stride = gridDim.x * blockDim.x;

    int i = blockIdx.x * blockDim.x + threadIdx.x;
    for (; i + stride < n4; i += 2 * stride) {
        uchar4 v0 = b[i];
        uchar4 v1 = b[i + stride];
        float4 r0, r1;
        r0.x = lut[v0.x]; r0.y = lut[v0.y]; r0.z = lut[v0.z]; r0.w = lut[v0.w];
        r1.x = lut[v1.x]; r1.y = lut[v1.y]; r1.z = lut[v1.z]; r1.w = lut[v1.w];
        q[i] = r0;
        q[i + stride] = r1;
    }
    if (i < n4) {
        uchar4 v = b[i];
        float4 r;
        r.x = lut[v.x]; r.y = lut[v.y]; r.z = lut[v.z]; r.w = lut[v.w];
        q[i] = r;
    }
}

extern "C" void kernel_launch(void* const* d_in, const int* in_sizes, int n_in,
                              void* d_out, int out_size) {
    const float* img = (const float*)d_in[0];
    float* out = (float*)d_out;
    const int npx = in_sizes[0] / NCH_TOTAL;   // 2048*4096

    zero_hist_kernel<<<3, 256>>>();
    copy_targets_kernel<<<dim3(1024, NCH_SAMPLE), 256>>>(img, out, npx);
    hist_bin_kernel<<<dim3(384, NCH_SAMPLE), 256>>>(img, npx);
    lut_kernel<<<NCH_SAMPLE, 256>>>();
    apply_samples_kernel<<<dim3(1024, NCH_SAMPLE), 256>>>(out, npx);
}